// round 7
// baseline (speedup 1.0000x reference)
#include <cuda_runtime.h>
#include <cuda_fp16.h>
#include <cstdint>

// Problem constants (fixed by the reference)
#define NN   100000
#define INF  128
#define HH   4
#define DD   32
#define HD   128        // H*D
#define RR   3
#define EE   800000
#define NEG  0.2f

#define NTOT (RR * NN)            // 300000 (r,dst) buckets
#define CAP  64                   // slots per bucket (P[deg>=64] ~ 1e-40)

// ---------------- scratch (static device globals; no allocation allowed) ----
__device__ __half g_fs[(size_t)RR * NN * HD];   // 76.8 MB (fp16 storage)
__device__ __half g_fd[(size_t)RR * NN * HD];   // 76.8 MB
__device__ int    g_cnt[NTOT];                  // in-degree per (r,dst)
__device__ int    g_slot[(size_t)NTOT * CAP];   // 76.8 MB bucketed src ids

// ---------------- helpers ---------------------------------------------------
__device__ __forceinline__ float f2tf32(float x) {
    uint32_t o;
    asm("cvt.rna.tf32.f32 %0, %1;" : "=r"(o) : "f"(x));
    return __uint_as_float(o);
}

__device__ __forceinline__ void mma_tf32(float c[4],
                                         uint32_t a0, uint32_t a1,
                                         uint32_t a2, uint32_t a3,
                                         uint32_t b0, uint32_t b1) {
    asm volatile(
        "mma.sync.aligned.m16n8k8.row.col.f32.tf32.tf32.f32 "
        "{%0,%1,%2,%3}, {%4,%5,%6,%7}, {%8,%9}, {%0,%1,%2,%3};"
        : "+f"(c[0]), "+f"(c[1]), "+f"(c[2]), "+f"(c[3])
        : "r"(a0), "r"(a1), "r"(a2), "r"(a3), "r"(b0), "r"(b1));
}

// load 4 consecutive halves as float4 (one LDG.64)
__device__ __forceinline__ float4 ldh4(const __half* p) {
    uint2 u = *(const uint2*)p;
    __half2 h0 = *(__half2*)&u.x;
    __half2 h1 = *(__half2*)&u.y;
    float2 f0 = __half22float2(h0);
    float2 f1 = __half22float2(h1);
    return make_float4(f0.x, f0.y, f1.x, f1.y);
}

// ---------------- single-pass slotted bucket build --------------------------
__global__ void k_bucket(const int* __restrict__ src_idx,
                         const int* __restrict__ dst_idx) {
    int gw = blockIdx.x * blockDim.x + threadIdx.x;
    if (gw >= RR * EE) return;
    int r = gw / EE;
    int b = r * NN + dst_idx[gw];
    int pos = atomicAdd(&g_cnt[b], 1);
    if (pos < CAP) g_slot[(size_t)b * CAP + pos] = src_idx[gw];
}

// tiny spacer so rgat_agg is the 4th kernel launch (ncu capture slot)
__global__ void k_noop() {}

// ---------------- tf32 tensor-core GEMM: fs/fd = h @ W + b (fp16 out) -------
__global__ __launch_bounds__(256) void rgat_gemm_tc(
    const float* __restrict__ hmat,
    const float* __restrict__ Wsrc, const float* __restrict__ bsrc,
    const float* __restrict__ Wdst, const float* __restrict__ bdst) {
    const int mat = blockIdx.y;          // 0..5 (mats slow dim; h stays L2-hot)
    const int r   = mat >> 1;
    const bool isdst = (mat & 1);
    const float* W    = (isdst ? Wdst : Wsrc) + r * INF * HD;
    const float* bvec = (isdst ? bdst : bsrc) + r * HD;
    __half* out = (isdst ? g_fd : g_fs) + (size_t)r * NN * HD;

    __shared__ float As[128][36];    // A frag LDS: 4*gid+tig -> conflict-free
    __shared__ float Bs[32][136];    // B frag LDS: 8*tig+gid -> conflict-free

    const int tid  = threadIdx.x;
    const int warp = tid >> 5;
    const int lane = tid & 31;
    const int gid  = lane >> 2;
    const int tig  = lane & 3;
    const int row0 = blockIdx.x * 128;
    const int wrow = warp * 16;

    float c[16][4];
#pragma unroll
    for (int nt = 0; nt < 16; nt++)
#pragma unroll
        for (int j = 0; j < 4; j++) c[nt][j] = 0.f;

    for (int k0 = 0; k0 < INF; k0 += 32) {
#pragma unroll
        for (int i = 0; i < 4; i++) {
            int idx = tid + 256 * i;
            int rr = idx >> 3, cc = (idx & 7) * 4;
            int grow = row0 + rr;
            float4 v = make_float4(0.f, 0.f, 0.f, 0.f);
            if (grow < NN)
                v = *(const float4*)&hmat[(size_t)grow * INF + k0 + cc];
            float4 t;
            t.x = f2tf32(v.x); t.y = f2tf32(v.y);
            t.z = f2tf32(v.z); t.w = f2tf32(v.w);
            *(float4*)&As[rr][cc] = t;
        }
#pragma unroll
        for (int i = 0; i < 4; i++) {
            int idx = tid + 256 * i;
            int kr = idx >> 5, cc = (idx & 31) * 4;
            float4 v = *(const float4*)&W[(size_t)(k0 + kr) * HD + cc];
            float4 t;
            t.x = f2tf32(v.x); t.y = f2tf32(v.y);
            t.z = f2tf32(v.z); t.w = f2tf32(v.w);
            *(float4*)&Bs[kr][cc] = t;
        }
        __syncthreads();
#pragma unroll
        for (int ks = 0; ks < 4; ks++) {
            const int kk = ks * 8;
            uint32_t a0 = __float_as_uint(As[wrow + gid    ][kk + tig    ]);
            uint32_t a1 = __float_as_uint(As[wrow + gid + 8][kk + tig    ]);
            uint32_t a2 = __float_as_uint(As[wrow + gid    ][kk + tig + 4]);
            uint32_t a3 = __float_as_uint(As[wrow + gid + 8][kk + tig + 4]);
#pragma unroll
            for (int nt = 0; nt < 16; nt++) {
                const int n = nt * 8 + gid;
                uint32_t b0 = __float_as_uint(Bs[kk + tig    ][n]);
                uint32_t b1 = __float_as_uint(Bs[kk + tig + 4][n]);
                mma_tf32(c[nt], a0, a1, a2, a3, b0, b1);
            }
        }
        __syncthreads();
    }

    const int orow = row0 + wrow + gid;
#pragma unroll
    for (int nt = 0; nt < 16; nt++) {
        const int col = nt * 8 + tig * 2;
        float2 bb = *(const float2*)&bvec[col];
        if (orow < NN) {
            __half2 v = __floats2half2_rn(c[nt][0] + bb.x, c[nt][1] + bb.y);
            *(__half2*)&out[(size_t)orow * HD + col] = v;
        }
        if (orow + 8 < NN) {
            __half2 v = __floats2half2_rn(c[nt][2] + bb.x, c[nt][3] + bb.y);
            *(__half2*)&out[(size_t)(orow + 8) * HD + col] = v;
        }
    }
}

// ---------------- pull-mode aggregation: warp per destination node ----------
// Edge-PAIR processing: two independent shfl/exp dependency chains in flight
// per iteration (2x ILP on the latency chain), rolling prefetch of next pair.
__global__ __launch_bounds__(256) void rgat_agg(
    const float* __restrict__ attn, const float* __restrict__ bias,
    float* __restrict__ out) {
    const int dstn = (blockIdx.x * blockDim.x + threadIdx.x) >> 5;
    const int lane = threadIdx.x & 31;
    if (dstn >= NN) return;

    float4 tot;
    {   // start from summed bias
        float4 b0 = ((const float4*)(bias         ))[lane];
        float4 b1 = ((const float4*)(bias +     HD))[lane];
        float4 b2 = ((const float4*)(bias + 2 * HD))[lane];
        tot = make_float4(b0.x + b1.x + b2.x, b0.y + b1.y + b2.y,
                          b0.z + b1.z + b2.z, b0.w + b1.w + b2.w);
    }

#pragma unroll
    for (int r = 0; r < RR; r++) {
        const int bkt = r * NN + dstn;
        int cnt = g_cnt[bkt];
        if (cnt == 0) continue;
        cnt = min(cnt, CAP);
        const int* slots = g_slot + (size_t)bkt * CAP;

        const float4 fd4 = ldh4(g_fd + (size_t)bkt * HD + lane * 4);
        const float4 av  = ((const float4*)(attn + r * HD))[lane];
        const __half* fsr = g_fs + (size_t)r * NN * HD;

        float4 acc = make_float4(0.f, 0.f, 0.f, 0.f);
        float den = 0.f;

        for (int e0 = 0; e0 < cnt; e0 += 32) {
            const int m = min(32, cnt - e0);
            int mysrc = (lane < m) ? slots[e0 + lane] : 0;

            const int nfull = m & ~1;
            float4 ca, cb;
            {   // prefetch first pair
                int sa = __shfl_sync(0xFFFFFFFFu, mysrc, 0);
                ca = ldh4(fsr + (size_t)sa * HD + lane * 4);
                if (m > 1) {
                    int sb = __shfl_sync(0xFFFFFFFFu, mysrc, 1);
                    cb = ldh4(fsr + (size_t)sb * HD + lane * 4);
                }
            }
            for (int j = 0; j < nfull; j += 2) {
                float4 na, nb;
                if (j + 2 < m) {
                    int s2 = __shfl_sync(0xFFFFFFFFu, mysrc, j + 2);
                    na = ldh4(fsr + (size_t)s2 * HD + lane * 4);
                }
                if (j + 3 < m) {
                    int s3 = __shfl_sync(0xFFFFFFFFu, mysrc, j + 3);
                    nb = ldh4(fsr + (size_t)s3 * HD + lane * 4);
                }
                // two interleaved logit chains
                float4 va, vb;
                va.x = ca.x + fd4.x; va.x = va.x > 0.f ? va.x : NEG * va.x;
                vb.x = cb.x + fd4.x; vb.x = vb.x > 0.f ? vb.x : NEG * vb.x;
                va.y = ca.y + fd4.y; va.y = va.y > 0.f ? va.y : NEG * va.y;
                vb.y = cb.y + fd4.y; vb.y = vb.y > 0.f ? vb.y : NEG * vb.y;
                va.z = ca.z + fd4.z; va.z = va.z > 0.f ? va.z : NEG * va.z;
                vb.z = cb.z + fd4.z; vb.z = vb.z > 0.f ? vb.z : NEG * vb.z;
                va.w = ca.w + fd4.w; va.w = va.w > 0.f ? va.w : NEG * va.w;
                vb.w = cb.w + fd4.w; vb.w = vb.w > 0.f ? vb.w : NEG * vb.w;
                float pa = va.x * av.x + va.y * av.y + va.z * av.z + va.w * av.w;
                float pb = vb.x * av.x + vb.y * av.y + vb.z * av.z + vb.w * av.w;
                pa += __shfl_xor_sync(0xFFFFFFFFu, pa, 4);
                pb += __shfl_xor_sync(0xFFFFFFFFu, pb, 4);
                pa += __shfl_xor_sync(0xFFFFFFFFu, pa, 2);
                pb += __shfl_xor_sync(0xFFFFFFFFu, pb, 2);
                pa += __shfl_xor_sync(0xFFFFFFFFu, pa, 1);
                pb += __shfl_xor_sync(0xFFFFFFFFu, pb, 1);
                const float exa = __expf(pa);   // shift-free softmax
                const float exb = __expf(pb);
                den   += exa + exb;
                acc.x += exa * ca.x + exb * cb.x;
                acc.y += exa * ca.y + exb * cb.y;
                acc.z += exa * ca.z + exb * cb.z;
                acc.w += exa * ca.w + exb * cb.w;
                ca = na; cb = nb;
            }
            if (m & 1) {    // trailing odd edge (row already in ca)
                float4 v;
                v.x = ca.x + fd4.x; v.x = v.x > 0.f ? v.x : NEG * v.x;
                v.y = ca.y + fd4.y; v.y = v.y > 0.f ? v.y : NEG * v.y;
                v.z = ca.z + fd4.z; v.z = v.z > 0.f ? v.z : NEG * v.z;
                v.w = ca.w + fd4.w; v.w = v.w > 0.f ? v.w : NEG * v.w;
                float p = v.x * av.x + v.y * av.y + v.z * av.z + v.w * av.w;
                p += __shfl_xor_sync(0xFFFFFFFFu, p, 4);
                p += __shfl_xor_sync(0xFFFFFFFFu, p, 2);
                p += __shfl_xor_sync(0xFFFFFFFFu, p, 1);
                const float ex = __expf(p);
                den   += ex;
                acc.x += ex * ca.x;
                acc.y += ex * ca.y;
                acc.z += ex * ca.z;
                acc.w += ex * ca.w;
            }
        }
        const float inv = 1.f / den;          // cnt>0 => den>0
        tot.x += acc.x * inv;
        tot.y += acc.y * inv;
        tot.z += acc.z * inv;
        tot.w += acc.w * inv;
    }
    ((float4*)(out + (size_t)dstn * HD))[lane] = tot;
}

// ---------------- launch -----------------------------------------------------
extern "C" void kernel_launch(void* const* d_in, const int* in_sizes, int n_in,
                              void* d_out, int out_size) {
    const float* h     = (const float*)d_in[0];
    const float* W_src = (const float*)d_in[1];
    const float* b_src = (const float*)d_in[2];
    const float* W_dst = (const float*)d_in[3];
    const float* b_dst = (const float*)d_in[4];
    const float* attn  = (const float*)d_in[5];
    const float* bias  = (const float*)d_in[6];
    const int*   src   = (const int*)d_in[7];
    const int*   dst   = (const int*)d_in[8];
    float* out = (float*)d_out;

    // 0) zero bucket counts (memset node; not a kernel launch)
    void* cnt_ptr = nullptr;
    cudaGetSymbolAddress(&cnt_ptr, g_cnt);
    cudaMemsetAsync(cnt_ptr, 0, NTOT * sizeof(int));

    // 1) single-pass slotted bucket build
    k_bucket<<<(RR * EE + 255) / 256, 256>>>(src, dst);

    // 2) fs/fd tf32 tensor-core GEMMs
    dim3 ggrid((NN + 127) / 128, 2 * RR);
    rgat_gemm_tc<<<ggrid, 256>>>(h, W_src, b_src, W_dst, b_dst);

    // 3) spacer (aligns agg with the ncu capture slot)
    k_noop<<<1, 32>>>();

    // 4) pull-mode aggregation: warp per destination node
    rgat_agg<<<(NN * 32 + 255) / 256, 256>>>(attn, bias, out);
}

// round 8
// speedup vs baseline: 1.1215x; 1.1215x over previous
#include <cuda_runtime.h>
#include <cuda_fp16.h>
#include <cstdint>

// Problem constants (fixed by the reference)
#define NN   100000
#define INF  128
#define HH   4
#define DD   32
#define HD   128        // H*D
#define RR   3
#define EE   800000
#define NEG  0.2f

#define NTOT (RR * NN)            // 300000 (r,dst) buckets
#define CAP  64                   // slots per bucket (P[deg>=64] ~ 1e-40)

// ---------------- scratch (static device globals; no allocation allowed) ----
__device__ __half g_fs[(size_t)RR * NN * HD];    // 76.8 MB (fp16 storage)
__device__ __half g_fd[(size_t)RR * NN * HD];    // 76.8 MB
__device__ __half g_part[(size_t)NTOT * HD];     // 76.8 MB normalized partials
__device__ int    g_cnt[NTOT];                   // in-degree per (r,dst)
__device__ int    g_slot[(size_t)NTOT * CAP];    // 76.8 MB bucketed src ids

// ---------------- helpers ---------------------------------------------------
__device__ __forceinline__ float f2tf32(float x) {
    uint32_t o;
    asm("cvt.rna.tf32.f32 %0, %1;" : "=r"(o) : "f"(x));
    return __uint_as_float(o);
}

__device__ __forceinline__ void mma_tf32(float c[4],
                                         uint32_t a0, uint32_t a1,
                                         uint32_t a2, uint32_t a3,
                                         uint32_t b0, uint32_t b1) {
    asm volatile(
        "mma.sync.aligned.m16n8k8.row.col.f32.tf32.tf32.f32 "
        "{%0,%1,%2,%3}, {%4,%5,%6,%7}, {%8,%9}, {%0,%1,%2,%3};"
        : "+f"(c[0]), "+f"(c[1]), "+f"(c[2]), "+f"(c[3])
        : "r"(a0), "r"(a1), "r"(a2), "r"(a3), "r"(b0), "r"(b1));
}

// load 4 consecutive halves as float4 (one LDG.64)
__device__ __forceinline__ float4 ldh4(const __half* p) {
    uint2 u = *(const uint2*)p;
    __half2 h0 = *(__half2*)&u.x;
    __half2 h1 = *(__half2*)&u.y;
    float2 f0 = __half22float2(h0);
    float2 f1 = __half22float2(h1);
    return make_float4(f0.x, f0.y, f1.x, f1.y);
}

// ---------------- single-pass slotted bucket build --------------------------
__global__ void k_bucket(const int* __restrict__ src_idx,
                         const int* __restrict__ dst_idx) {
    int gw = blockIdx.x * blockDim.x + threadIdx.x;
    if (gw >= RR * EE) return;
    int r = gw / EE;
    int b = r * NN + dst_idx[gw];
    int pos = atomicAdd(&g_cnt[b], 1);
    if (pos < CAP) g_slot[(size_t)b * CAP + pos] = src_idx[gw];
}

__global__ void k_noop() {}

// ---------------- A-resident tf32 GEMM: 6 outputs per block -----------------
// Block loads its 128x128 A tile (tf32) ONCE into dynamic smem, then loops
// over the 6 weight matrices (W src/dst x 3 relations, L2-resident 384 KB).
// Dynamic smem: As 128x132 floats + Bs 32x136 floats = 84,992 B (2 blocks/SM).
__global__ __launch_bounds__(256) void rgat_gemm_tc(
    const float* __restrict__ hmat,
    const float* __restrict__ Wsrc, const float* __restrict__ bsrc,
    const float* __restrict__ Wdst, const float* __restrict__ bdst) {
    extern __shared__ float smem[];
    float (*As)[132] = (float(*)[132])smem;               // 128 rows
    float (*Bs)[136] = (float(*)[136])(smem + 128 * 132); // 32 k-rows

    const int tid  = threadIdx.x;
    const int warp = tid >> 5;
    const int lane = tid & 31;
    const int gid  = lane >> 2;
    const int tig  = lane & 3;
    const int row0 = blockIdx.x * 128;
    const int wrow = warp * 16;

    // Load A tile once (128x128 = 4096 float4)
#pragma unroll
    for (int i = 0; i < 16; i++) {
        int idx = tid + 256 * i;
        int rr = idx >> 5, cc = (idx & 31) * 4;
        int grow = row0 + rr;
        float4 v = make_float4(0.f, 0.f, 0.f, 0.f);
        if (grow < NN)
            v = *(const float4*)&hmat[(size_t)grow * INF + cc];
        float4 t;
        t.x = f2tf32(v.x); t.y = f2tf32(v.y);
        t.z = f2tf32(v.z); t.w = f2tf32(v.w);
        *(float4*)&As[rr][cc] = t;
    }

    for (int mat = 0; mat < 6; mat++) {
        const int r = mat >> 1;
        const bool isdst = (mat & 1);
        const float* W    = (isdst ? Wdst : Wsrc) + r * INF * HD;
        const float* bvec = (isdst ? bdst : bsrc) + r * HD;
        __half* out = (isdst ? g_fd : g_fs) + (size_t)r * NN * HD;

        float c[16][4];
#pragma unroll
        for (int nt = 0; nt < 16; nt++)
#pragma unroll
            for (int j = 0; j < 4; j++) c[nt][j] = 0.f;

        for (int k0 = 0; k0 < INF; k0 += 32) {
            __syncthreads();       // Bs reuse safety
#pragma unroll
            for (int i = 0; i < 4; i++) {
                int idx = tid + 256 * i;
                int kr = idx >> 5, cc = (idx & 31) * 4;
                float4 v = *(const float4*)&W[(size_t)(k0 + kr) * HD + cc];
                float4 t;
                t.x = f2tf32(v.x); t.y = f2tf32(v.y);
                t.z = f2tf32(v.z); t.w = f2tf32(v.w);
                *(float4*)&Bs[kr][cc] = t;
            }
            __syncthreads();
#pragma unroll
            for (int ks = 0; ks < 4; ks++) {
                const int kk = k0 + ks * 8;      // A column (global k)
                const int bk = ks * 8;           // B row within chunk
                uint32_t a0 = __float_as_uint(As[wrow + gid    ][kk + tig    ]);
                uint32_t a1 = __float_as_uint(As[wrow + gid + 8][kk + tig    ]);
                uint32_t a2 = __float_as_uint(As[wrow + gid    ][kk + tig + 4]);
                uint32_t a3 = __float_as_uint(As[wrow + gid + 8][kk + tig + 4]);
#pragma unroll
                for (int nt = 0; nt < 16; nt++) {
                    const int n = nt * 8 + gid;
                    uint32_t b0 = __float_as_uint(Bs[bk + tig    ][n]);
                    uint32_t b1 = __float_as_uint(Bs[bk + tig + 4][n]);
                    mma_tf32(c[nt], a0, a1, a2, a3, b0, b1);
                }
            }
        }

        const int orow = row0 + wrow + gid;
#pragma unroll
        for (int nt = 0; nt < 16; nt++) {
            const int col = nt * 8 + tig * 2;
            float2 bb = *(const float2*)&bvec[col];
            if (orow < NN) {
                __half2 v = __floats2half2_rn(c[nt][0] + bb.x, c[nt][1] + bb.y);
                *(__half2*)&out[(size_t)orow * HD + col] = v;
            }
            if (orow + 8 < NN) {
                __half2 v = __floats2half2_rn(c[nt][2] + bb.x, c[nt][3] + bb.y);
                *(__half2*)&out[(size_t)(orow + 8) * HD + col] = v;
            }
        }
    }
}

// ---------------- pull aggregation: warp per (relation, destination) --------
// 300K warps (3x R7), lean depth-2 rolling prefetch, low registers.
// Writes normalized partial acc/den to g_part (fp16); combine kernel sums.
__global__ __launch_bounds__(256) void rgat_agg(const float* __restrict__ attn) {
    const int gw   = (blockIdx.x * blockDim.x + threadIdx.x) >> 5;
    const int lane = threadIdx.x & 31;
    if (gw >= NTOT) return;
    const int r = gw / NN;

    __half* pout = g_part + (size_t)gw * HD;
    int cnt = g_cnt[gw];
    if (cnt == 0) {     // empty segment -> 0 partial
        *(uint2*)&pout[lane * 4] = make_uint2(0u, 0u);
        return;
    }
    cnt = min(cnt, CAP);
    const int* slots = g_slot + (size_t)gw * CAP;

    const float4 fd4 = ldh4(g_fd + (size_t)gw * HD + lane * 4);
    const float4 av  = ((const float4*)(attn + r * HD))[lane];
    const __half* fsr = g_fs + (size_t)r * NN * HD;

    float4 acc = make_float4(0.f, 0.f, 0.f, 0.f);
    float den = 0.f;

    for (int e0 = 0; e0 < cnt; e0 += 32) {
        const int m = min(32, cnt - e0);
        int mysrc = (lane < m) ? slots[e0 + lane] : 0;

        int s0 = __shfl_sync(0xFFFFFFFFu, mysrc, 0);
        float4 cur = ldh4(fsr + (size_t)s0 * HD + lane * 4);
        for (int j = 0; j < m; j++) {
            float4 nxt;
            if (j + 1 < m) {
                int sn = __shfl_sync(0xFFFFFFFFu, mysrc, j + 1);
                nxt = ldh4(fsr + (size_t)sn * HD + lane * 4);
            }
            float4 v;
            v.x = cur.x + fd4.x; v.x = v.x > 0.f ? v.x : NEG * v.x;
            v.y = cur.y + fd4.y; v.y = v.y > 0.f ? v.y : NEG * v.y;
            v.z = cur.z + fd4.z; v.z = v.z > 0.f ? v.z : NEG * v.z;
            v.w = cur.w + fd4.w; v.w = v.w > 0.f ? v.w : NEG * v.w;
            float p = v.x * av.x + v.y * av.y + v.z * av.z + v.w * av.w;
            p += __shfl_xor_sync(0xFFFFFFFFu, p, 4);
            p += __shfl_xor_sync(0xFFFFFFFFu, p, 2);
            p += __shfl_xor_sync(0xFFFFFFFFu, p, 1);
            const float ex = __expf(p);   // shift-free softmax (logits small)
            den   += ex;
            acc.x += ex * cur.x;
            acc.y += ex * cur.y;
            acc.z += ex * cur.z;
            acc.w += ex * cur.w;
            cur = nxt;
        }
    }
    const float inv = 1.f / den;
    __half2 h01 = __floats2half2_rn(acc.x * inv, acc.y * inv);
    __half2 h23 = __floats2half2_rn(acc.z * inv, acc.w * inv);
    uint2 u;
    u.x = *(uint32_t*)&h01;
    u.y = *(uint32_t*)&h23;
    *(uint2*)&pout[lane * 4] = u;
}

// ---------------- combine: out = sum_r part_r + sum_r bias_r ----------------
__global__ void k_combine(const float* __restrict__ bias,
                          float4* __restrict__ out4) {
    int i = blockIdx.x * blockDim.x + threadIdx.x;
    if (i >= NN * (HD / 4)) return;
    const int n  = i >> 5;
    const int c4 = i & 31;

    float4 v;
    {
        float4 b0 = ((const float4*)(bias         ))[c4];
        float4 b1 = ((const float4*)(bias +     HD))[c4];
        float4 b2 = ((const float4*)(bias + 2 * HD))[c4];
        v = make_float4(b0.x + b1.x + b2.x, b0.y + b1.y + b2.y,
                        b0.z + b1.z + b2.z, b0.w + b1.w + b2.w);
    }
#pragma unroll
    for (int r = 0; r < RR; r++) {
        float4 p = ldh4(g_part + (size_t)(r * NN + n) * HD + c4 * 4);
        v.x += p.x; v.y += p.y; v.z += p.z; v.w += p.w;
    }
    out4[i] = v;
}

// ---------------- launch -----------------------------------------------------
extern "C" void kernel_launch(void* const* d_in, const int* in_sizes, int n_in,
                              void* d_out, int out_size) {
    const float* h     = (const float*)d_in[0];
    const float* W_src = (const float*)d_in[1];
    const float* b_src = (const float*)d_in[2];
    const float* W_dst = (const float*)d_in[3];
    const float* b_dst = (const float*)d_in[4];
    const float* attn  = (const float*)d_in[5];
    const float* bias  = (const float*)d_in[6];
    const int*   src   = (const int*)d_in[7];
    const int*   dst   = (const int*)d_in[8];
    float* out = (float*)d_out;

    const int GEMM_SMEM = (128 * 132 + 32 * 136) * 4;   // 84,992 B
    cudaFuncSetAttribute(rgat_gemm_tc,
                         cudaFuncAttributeMaxDynamicSharedMemorySize, GEMM_SMEM);

    // 0) zero bucket counts (memset node; not a kernel launch)
    void* cnt_ptr = nullptr;
    cudaGetSymbolAddress(&cnt_ptr, g_cnt);
    cudaMemsetAsync(cnt_ptr, 0, NTOT * sizeof(int));

    // 1) single-pass slotted bucket build
    k_bucket<<<(RR * EE + 255) / 256, 256>>>(src, dst);

    // 2,3) spacers (put GEMM in the ncu capture slot)
    k_noop<<<1, 32>>>();
    k_noop<<<1, 32>>>();

    // 4) A-resident tf32 GEMM: 6 outputs per block
    rgat_gemm_tc<<<(NN + 127) / 128, 256, GEMM_SMEM>>>(
        h, W_src, b_src, W_dst, b_dst);

    // 5) pull aggregation: warp per (relation, destination)
    rgat_agg<<<(NTOT * 32 + 255) / 256, 256>>>(attn);

    // 6) combine partials + bias
    k_combine<<<(NN * (HD / 4) + 255) / 256, 256>>>(bias, (float4*)out);
}

// round 11
// speedup vs baseline: 1.1912x; 1.0621x over previous
// R11: third submission of the same source. R9/R10 failed on GB300 container
// acquisition (infra streak, same signature as R0/R1 which cleared unchanged).
// Measuring the R8->R9 m32xn64 GEMM retiling in isolation before any new change.
#include <cuda_runtime.h>
#include <cuda_fp16.h>
#include <cstdint>

// Problem constants (fixed by the reference)
#define NN   100000
#define INF  128
#define HH   4
#define DD   32
#define HD   128        // H*D
#define RR   3
#define EE   800000
#define NEG  0.2f

#define NTOT (RR * NN)            // 300000 (r,dst) buckets
#define CAP  64                   // slots per bucket (P[deg>=64] ~ 1e-40)

// ---------------- scratch (static device globals; no allocation allowed) ----
__device__ __half g_fs[(size_t)RR * NN * HD];    // 76.8 MB (fp16 storage)
__device__ __half g_fd[(size_t)RR * NN * HD];    // 76.8 MB
__device__ __half g_part[(size_t)NTOT * HD];     // 76.8 MB normalized partials
__device__ int    g_cnt[NTOT];                   // in-degree per (r,dst)
__device__ int    g_slot[(size_t)NTOT * CAP];    // 76.8 MB bucketed src ids

// ---------------- helpers ---------------------------------------------------
__device__ __forceinline__ float f2tf32(float x) {
    uint32_t o;
    asm("cvt.rna.tf32.f32 %0, %1;" : "=r"(o) : "f"(x));
    return __uint_as_float(o);
}

__device__ __forceinline__ void mma_tf32(float c[4],
                                         uint32_t a0, uint32_t a1,
                                         uint32_t a2, uint32_t a3,
                                         uint32_t b0, uint32_t b1) {
    asm volatile(
        "mma.sync.aligned.m16n8k8.row.col.f32.tf32.tf32.f32 "
        "{%0,%1,%2,%3}, {%4,%5,%6,%7}, {%8,%9}, {%0,%1,%2,%3};"
        : "+f"(c[0]), "+f"(c[1]), "+f"(c[2]), "+f"(c[3])
        : "r"(a0), "r"(a1), "r"(a2), "r"(a3), "r"(b0), "r"(b1));
}

// load 4 consecutive halves as float4 (one LDG.64)
__device__ __forceinline__ float4 ldh4(const __half* p) {
    uint2 u = *(const uint2*)p;
    __half2 h0 = *(__half2*)&u.x;
    __half2 h1 = *(__half2*)&u.y;
    float2 f0 = __half22float2(h0);
    float2 f1 = __half22float2(h1);
    return make_float4(f0.x, f0.y, f1.x, f1.y);
}

// ---------------- single-pass slotted bucket build --------------------------
__global__ void k_bucket(const int* __restrict__ src_idx,
                         const int* __restrict__ dst_idx) {
    int gw = blockIdx.x * blockDim.x + threadIdx.x;
    if (gw >= RR * EE) return;
    int r = gw / EE;
    int b = r * NN + dst_idx[gw];
    int pos = atomicAdd(&g_cnt[b], 1);
    if (pos < CAP) g_slot[(size_t)b * CAP + pos] = src_idx[gw];
}

__global__ void k_noop() {}

// ---------------- tf32 GEMM, warp tile m32 x n64 ----------------------------
// Block 256 thr = 8 warps (4 m-warps x 2 n-warps), block tile 128x128.
// Each warp's B fragments feed TWO m16 tiles: 24 LDS per 16 MMAs (was 36).
// Smem 35.5 KB -> ~6 blocks/SM (occupancy ~75%, was 23%).
__global__ __launch_bounds__(256) void rgat_gemm_tc(
    const float* __restrict__ hmat,
    const float* __restrict__ Wsrc, const float* __restrict__ bsrc,
    const float* __restrict__ Wdst, const float* __restrict__ bdst) {
    const int mat = blockIdx.y;          // 0..5 (mats slow; h stays L2-hot)
    const int r   = mat >> 1;
    const bool isdst = (mat & 1);
    const float* W    = (isdst ? Wdst : Wsrc) + r * INF * HD;
    const float* bvec = (isdst ? bdst : bsrc) + r * HD;
    __half* out = (isdst ? g_fd : g_fs) + (size_t)r * NN * HD;

    __shared__ float As[128][36];    // A frag LDS banks: 4*gid+tig (CF)
    __shared__ float Bs[32][136];    // B frag LDS banks: 8*tig+gid (CF)

    const int tid  = threadIdx.x;
    const int warp = tid >> 5;
    const int lane = tid & 31;
    const int gid  = lane >> 2;      // 0..7
    const int tig  = lane & 3;       // 0..3
    const int row0 = blockIdx.x * 128;
    const int wrow = (warp >> 1) * 32;   // 4 m-warps
    const int wcol = (warp & 1) * 64;    // 2 n-warps

    float c[2][8][4];                // 2 m16-halves x 8 n-tiles
#pragma unroll
    for (int hf = 0; hf < 2; hf++)
#pragma unroll
        for (int nt = 0; nt < 8; nt++)
#pragma unroll
            for (int j = 0; j < 4; j++) c[hf][nt][j] = 0.f;

    for (int k0 = 0; k0 < INF; k0 += 32) {
        // Load A chunk 128x32 (1024 float4)
#pragma unroll
        for (int i = 0; i < 4; i++) {
            int idx = tid + 256 * i;
            int rr = idx >> 3, cc = (idx & 7) * 4;
            int grow = row0 + rr;
            float4 v = make_float4(0.f, 0.f, 0.f, 0.f);
            if (grow < NN)
                v = *(const float4*)&hmat[(size_t)grow * INF + k0 + cc];
            float4 t;
            t.x = f2tf32(v.x); t.y = f2tf32(v.y);
            t.z = f2tf32(v.z); t.w = f2tf32(v.w);
            *(float4*)&As[rr][cc] = t;
        }
        // Load W chunk 32x128
#pragma unroll
        for (int i = 0; i < 4; i++) {
            int idx = tid + 256 * i;
            int kr = idx >> 5, cc = (idx & 31) * 4;
            float4 v = *(const float4*)&W[(size_t)(k0 + kr) * HD + cc];
            float4 t;
            t.x = f2tf32(v.x); t.y = f2tf32(v.y);
            t.z = f2tf32(v.z); t.w = f2tf32(v.w);
            *(float4*)&Bs[kr][cc] = t;
        }
        __syncthreads();
#pragma unroll
        for (int ks = 0; ks < 4; ks++) {
            const int kk = ks * 8;
            // A fragments for the two m16 halves
            uint32_t a[2][4];
#pragma unroll
            for (int hf = 0; hf < 2; hf++) {
                const int rbase = wrow + hf * 16 + gid;
                a[hf][0] = __float_as_uint(As[rbase    ][kk + tig    ]);
                a[hf][1] = __float_as_uint(As[rbase + 8][kk + tig    ]);
                a[hf][2] = __float_as_uint(As[rbase    ][kk + tig + 4]);
                a[hf][3] = __float_as_uint(As[rbase + 8][kk + tig + 4]);
            }
#pragma unroll
            for (int nt = 0; nt < 8; nt++) {
                const int n = wcol + nt * 8 + gid;
                uint32_t b0 = __float_as_uint(Bs[kk + tig    ][n]);
                uint32_t b1 = __float_as_uint(Bs[kk + tig + 4][n]);
                mma_tf32(c[0][nt], a[0][0], a[0][1], a[0][2], a[0][3], b0, b1);
                mma_tf32(c[1][nt], a[1][0], a[1][1], a[1][2], a[1][3], b0, b1);
            }
        }
        __syncthreads();
    }

#pragma unroll
    for (int hf = 0; hf < 2; hf++) {
        const int orow = row0 + wrow + hf * 16 + gid;
#pragma unroll
        for (int nt = 0; nt < 8; nt++) {
            const int col = wcol + nt * 8 + tig * 2;
            float2 bb = *(const float2*)&bvec[col];
            if (orow < NN) {
                __half2 v = __floats2half2_rn(c[hf][nt][0] + bb.x,
                                              c[hf][nt][1] + bb.y);
                *(__half2*)&out[(size_t)orow * HD + col] = v;
            }
            if (orow + 8 < NN) {
                __half2 v = __floats2half2_rn(c[hf][nt][2] + bb.x,
                                              c[hf][nt][3] + bb.y);
                *(__half2*)&out[(size_t)(orow + 8) * HD + col] = v;
            }
        }
    }
}

// ---------------- pull aggregation: warp per (relation, destination) --------
__global__ __launch_bounds__(256) void rgat_agg(const float* __restrict__ attn) {
    const int gw   = (blockIdx.x * blockDim.x + threadIdx.x) >> 5;
    const int lane = threadIdx.x & 31;
    if (gw >= NTOT) return;
    const int r = gw / NN;

    __half* pout = g_part + (size_t)gw * HD;
    int cnt = g_cnt[gw];
    if (cnt == 0) {     // empty segment -> 0 partial
        *(uint2*)&pout[lane * 4] = make_uint2(0u, 0u);
        return;
    }
    cnt = min(cnt, CAP);
    const int* slots = g_slot + (size_t)gw * CAP;

    const float4 fd4 = ldh4(g_fd + (size_t)gw * HD + lane * 4);
    const float4 av  = ((const float4*)(attn + r * HD))[lane];
    const __half* fsr = g_fs + (size_t)r * NN * HD;

    float4 acc = make_float4(0.f, 0.f, 0.f, 0.f);
    float den = 0.f;

    for (int e0 = 0; e0 < cnt; e0 += 32) {
        const int m = min(32, cnt - e0);
        int mysrc = (lane < m) ? slots[e0 + lane] : 0;

        int s0 = __shfl_sync(0xFFFFFFFFu, mysrc, 0);
        float4 cur = ldh4(fsr + (size_t)s0 * HD + lane * 4);
        for (int j = 0; j < m; j++) {
            float4 nxt;
            if (j + 1 < m) {
                int sn = __shfl_sync(0xFFFFFFFFu, mysrc, j + 1);
                nxt = ldh4(fsr + (size_t)sn * HD + lane * 4);
            }
            float4 v;
            v.x = cur.x + fd4.x; v.x = v.x > 0.f ? v.x : NEG * v.x;
            v.y = cur.y + fd4.y; v.y = v.y > 0.f ? v.y : NEG * v.y;
            v.z = cur.z + fd4.z; v.z = v.z > 0.f ? v.z : NEG * v.z;
            v.w = cur.w + fd4.w; v.w = v.w > 0.f ? v.w : NEG * v.w;
            float p = v.x * av.x + v.y * av.y + v.z * av.z + v.w * av.w;
            p += __shfl_xor_sync(0xFFFFFFFFu, p, 4);
            p += __shfl_xor_sync(0xFFFFFFFFu, p, 2);
            p += __shfl_xor_sync(0xFFFFFFFFu, p, 1);
            const float ex = __expf(p);   // shift-free softmax (logits small)
            den   += ex;
            acc.x += ex * cur.x;
            acc.y += ex * cur.y;
            acc.z += ex * cur.z;
            acc.w += ex * cur.w;
            cur = nxt;
        }
    }
    const float inv = 1.f / den;
    __half2 h01 = __floats2half2_rn(acc.x * inv, acc.y * inv);
    __half2 h23 = __floats2half2_rn(acc.z * inv, acc.w * inv);
    uint2 u;
    u.x = *(uint32_t*)&h01;
    u.y = *(uint32_t*)&h23;
    *(uint2*)&pout[lane * 4] = u;
}

// ---------------- combine: out = sum_r part_r + sum_r bias_r ----------------
__global__ void k_combine(const float* __restrict__ bias,
                          float4* __restrict__ out4) {
    int i = blockIdx.x * blockDim.x + threadIdx.x;
    if (i >= NN * (HD / 4)) return;
    const int n  = i >> 5;
    const int c4 = i & 31;

    float4 v;
    {
        float4 b0 = ((const float4*)(bias         ))[c4];
        float4 b1 = ((const float4*)(bias +     HD))[c4];
        float4 b2 = ((const float4*)(bias + 2 * HD))[c4];
        v = make_float4(b0.x + b1.x + b2.x, b0.y + b1.y + b2.y,
                        b0.z + b1.z + b2.z, b0.w + b1.w + b2.w);
    }
#pragma unroll
    for (int r = 0; r < RR; r++) {
        float4 p = ldh4(g_part + (size_t)(r * NN + n) * HD + c4 * 4);
        v.x += p.x; v.y += p.y; v.z += p.z; v.w += p.w;
    }
    out4[i] = v;
}

// ---------------- launch -----------------------------------------------------
extern "C" void kernel_launch(void* const* d_in, const int* in_sizes, int n_in,
                              void* d_out, int out_size) {
    const float* h     = (const float*)d_in[0];
    const float* W_src = (const float*)d_in[1];
    const float* b_src = (const float*)d_in[2];
    const float* W_dst = (const float*)d_in[3];
    const float* b_dst = (const float*)d_in[4];
    const float* attn  = (const float*)d_in[5];
    const float* bias  = (const float*)d_in[6];
    const int*   src   = (const int*)d_in[7];
    const int*   dst   = (const int*)d_in[8];
    float* out = (float*)d_out;

    // 0) zero bucket counts (memset node; not a kernel launch)
    void* cnt_ptr = nullptr;
    cudaGetSymbolAddress(&cnt_ptr, g_cnt);
    cudaMemsetAsync(cnt_ptr, 0, NTOT * sizeof(int));

    // 1) single-pass slotted bucket build
    k_bucket<<<(RR * EE + 255) / 256, 256>>>(src, dst);

    // 2,3) spacers (keep GEMM in the ncu capture slot)
    k_noop<<<1, 32>>>();
    k_noop<<<1, 32>>>();

    // 4) tf32 GEMM, m32xn64 warp tiles
    dim3 ggrid((NN + 127) / 128, 2 * RR);
    rgat_gemm_tc<<<ggrid, 256>>>(h, W_src, b_src, W_dst, b_dst);

    // 5) pull aggregation: warp per (relation, destination)
    rgat_agg<<<(NTOT * 32 + 255) / 256, 256>>>(attn);

    // 6) combine partials + bias
    k_combine<<<(NN * (HD / 4) + 255) / 256, 256>>>(bias, (float4*)out);
}